// round 4
// baseline (speedup 1.0000x reference)
#include <cuda_runtime.h>
#include <math.h>

#define N_  131072
#define D_  512
#define M_  4
#define K_  256
#define DM_ 128
#define PAD 129
#define TILE_N 64

// Scratch: xr = x @ rotate (268 MB). __device__ globals are the sanctioned scratch.
__device__ float  g_xr[N_ * D_];
__device__ double g_acc[4];   // s_soft, s_hard, s_joint, s_reg

// ---------------------------------------------------------------------------
// Kernel 0: zero accumulators
// ---------------------------------------------------------------------------
__global__ void zero_acc_kernel() {
    if (threadIdx.x < 4) g_acc[threadIdx.x] = 0.0;
}

// ---------------------------------------------------------------------------
// Kernel 1: xr = x @ rotate   (N_ x D_) = (N_ x D_) @ (D_ x D_), fp32 SGEMM
// 128x128 block tile, BK=8, 256 threads, 8x8 per thread.
// ---------------------------------------------------------------------------
__global__ void __launch_bounds__(256) sgemm_xr_kernel(
    const float* __restrict__ A, const float* __restrict__ B)
{
    __shared__ float As[8][128];
    __shared__ float Bs[8][128];

    const int bx = blockIdx.x;          // over D_/128 = 4
    const int by = blockIdx.y;          // over N_/128 = 1024
    const int tid = threadIdx.x;
    const int tx = tid & 15;            // 0..15
    const int ty = tid >> 4;            // 0..15

    const float* Ablk = A + (size_t)by * 128 * D_;
    const float* Bblk = B + bx * 128;

    const int arow = tid >> 1;          // 0..127
    const int acol = (tid & 1) * 4;     // 0 or 4
    const int brow = tid >> 5;          // 0..7
    const int bcol = (tid & 31) * 4;    // 0..124

    float acc[8][8];
#pragma unroll
    for (int i = 0; i < 8; ++i)
#pragma unroll
        for (int j = 0; j < 8; ++j) acc[i][j] = 0.f;

    for (int k0 = 0; k0 < D_; k0 += 8) {
        float4 av = *(const float4*)(Ablk + (size_t)arow * D_ + k0 + acol);
        float4 bv = *(const float4*)(Bblk + (size_t)(k0 + brow) * D_ + bcol);
        As[acol + 0][arow] = av.x;
        As[acol + 1][arow] = av.y;
        As[acol + 2][arow] = av.z;
        As[acol + 3][arow] = av.w;
        *(float4*)&Bs[brow][bcol] = bv;
        __syncthreads();

#pragma unroll
        for (int kk = 0; kk < 8; ++kk) {
            float4 a0 = *(const float4*)&As[kk][ty * 8];
            float4 a1 = *(const float4*)&As[kk][ty * 8 + 4];
            float4 b0 = *(const float4*)&Bs[kk][tx * 8];
            float4 b1 = *(const float4*)&Bs[kk][tx * 8 + 4];
            float ar[8] = {a0.x, a0.y, a0.z, a0.w, a1.x, a1.y, a1.z, a1.w};
            float br[8] = {b0.x, b0.y, b0.z, b0.w, b1.x, b1.y, b1.z, b1.w};
#pragma unroll
            for (int i = 0; i < 8; ++i)
#pragma unroll
                for (int j = 0; j < 8; ++j)
                    acc[i][j] = fmaf(ar[i], br[j], acc[i][j]);
        }
        __syncthreads();
    }

#pragma unroll
    for (int i = 0; i < 8; ++i) {
        const int row = by * 128 + ty * 8 + i;
        float* cp = g_xr + (size_t)row * D_ + bx * 128 + tx * 8;
        *(float4*)cp       = make_float4(acc[i][0], acc[i][1], acc[i][2], acc[i][3]);
        *(float4*)(cp + 4) = make_float4(acc[i][4], acc[i][5], acc[i][6], acc[i][7]);
    }
}

// ---------------------------------------------------------------------------
// Kernel 2: per (n,m): distances to 256 codewords, softmax, argmax, soft/hard
// reconstructions, loss partials. One block per (64-row n-tile, m).
// Dynamic smem:
//   sp4    [128] float4 : splits for 4 n-rows, interleaved per d
//   probs4 [256] float4 : softmax probs for 4 n-rows, interleaved per k
//   softp4 [128] float4 : partial soft sums (k=128..255 half)
//   cb_s   [256*129]    : codebook[m], row pad 129 (conflict-free both axes)
//   red    [64]         : reduction scratch (vals + idx)
//   bcf    [16] / bci[4]: broadcast slots
// ---------------------------------------------------------------------------
#define SMEM_FLOATS (512 + 1024 + 512 + K_ * PAD + 64 + 16 + 4)
#define SMEM_BYTES  (SMEM_FLOATS * 4)

__global__ void __launch_bounds__(256) dist_kernel(
    const float* __restrict__ cb, float* __restrict__ out)
{
    extern __shared__ float smem[];
    float4* sp4    = (float4*)smem;                 // 128 float4
    float4* probs4 = sp4 + 128;                     // 256 float4
    float4* softp4 = probs4 + 256;                  // 128 float4
    float*  cb_s   = (float*)(softp4 + 128);        // 256*129
    float*  red    = cb_s + K_ * PAD;               // 64
    float*  bcf    = red + 64;                      // 16
    int*    bci    = (int*)(bcf + 16);              // 4

    const int m    = blockIdx.y;
    const int tid  = threadIdx.x;
    const int lane = tid & 31;
    const int warp = tid >> 5;

    // load codebook[m] into smem
    const float* cbm = cb + (size_t)m * K_ * DM_;
    for (int idx = tid; idx < K_ * DM_; idx += 256)
        cb_s[(idx >> 7) * PAD + (idx & 127)] = cbm[idx];
    __syncthreads();

    // c2[k] for this thread's k = tid
    float c2 = 0.f;
    {
        const float* crow = cb_s + tid * PAD;
#pragma unroll 8
        for (int d = 0; d < DM_; ++d) { float c = crow[d]; c2 = fmaf(c, c, c2); }
    }

    float acc1 = 0.f, acc2 = 0.f, acc3 = 0.f;
    const int nbase = blockIdx.x * TILE_N;

    for (int g = 0; g < TILE_N; g += 4) {
        const int n0 = nbase + g;

        // ---- load splits for 4 n-rows (interleaved) ----
        {
            int idx = tid;
            int j = idx >> 7, d = idx & 127;
            ((float*)sp4)[d * 4 + j] = g_xr[(size_t)(n0 + j) * D_ + m * DM_ + d];
            idx = tid + 256; j = idx >> 7; d = idx & 127;
            ((float*)sp4)[d * 4 + j] = g_xr[(size_t)(n0 + j) * D_ + m * DM_ + d];
        }
        __syncthreads();

        // ---- x2 per n (warps 0..3, one component each) ----
        if (warp < 4) {
            float v = 0.f;
#pragma unroll
            for (int d = lane; d < DM_; d += 32) {
                float s = ((float*)sp4)[d * 4 + warp];
                v = fmaf(s, s, v);
            }
#pragma unroll
            for (int off = 16; off; off >>= 1)
                v += __shfl_down_sync(0xffffffffu, v, off);
            if (lane == 0) bcf[warp] = v;
        }
        __syncthreads();

        // ---- xc for this thread's k, 4 n-rows ----
        float4 xc = make_float4(0.f, 0.f, 0.f, 0.f);
        {
            const float* crow = cb_s + tid * PAD;
#pragma unroll 16
            for (int d = 0; d < DM_; ++d) {
                float c = crow[d];
                float4 s = sp4[d];
                xc.x = fmaf(c, s.x, xc.x);
                xc.y = fmaf(c, s.y, xc.y);
                xc.z = fmaf(c, s.z, xc.z);
                xc.w = fmaf(c, s.w, xc.w);
            }
        }
        float dist[4];
        dist[0] = bcf[0] - 2.f * xc.x + c2;
        dist[1] = bcf[1] - 2.f * xc.y + c2;
        dist[2] = bcf[2] - 2.f * xc.z + c2;
        dist[3] = bcf[3] - 2.f * xc.w + c2;

        // ---- argmin reduction (min dist, lowest k on ties == jnp.argmax) ----
#pragma unroll
        for (int j = 0; j < 4; ++j) {
            float dv = dist[j]; int iv = tid;
#pragma unroll
            for (int off = 16; off; off >>= 1) {
                float od = __shfl_down_sync(0xffffffffu, dv, off);
                int   oi = __shfl_down_sync(0xffffffffu, iv, off);
                if (od < dv || (od == dv && oi < iv)) { dv = od; iv = oi; }
            }
            if (lane == 0) {
                red[j * 8 + warp] = dv;
                ((int*)red)[32 + j * 8 + warp] = iv;
            }
        }
        __syncthreads();
        if (tid < 4) {
            float dv = red[tid * 8]; int iv = ((int*)red)[32 + tid * 8];
#pragma unroll
            for (int w = 1; w < 8; ++w) {
                float od = red[tid * 8 + w]; int oi = ((int*)red)[32 + tid * 8 + w];
                if (od < dv || (od == dv && oi < iv)) { dv = od; iv = oi; }
            }
            bcf[4 + tid] = dv;
            bci[tid] = iv;
            out[(size_t)(n0 + tid) * M_ + m] = (float)iv;   // hard code
        }
        __syncthreads();

        // ---- exp + sum ----
        float e[4];
#pragma unroll
        for (int j = 0; j < 4; ++j) e[j] = expf(bcf[4 + j] - dist[j]);
#pragma unroll
        for (int j = 0; j < 4; ++j) {
            float sv = e[j];
#pragma unroll
            for (int off = 16; off; off >>= 1)
                sv += __shfl_down_sync(0xffffffffu, sv, off);
            if (lane == 0) red[j * 8 + warp] = sv;
        }
        __syncthreads();
        if (tid < 4) {
            float sv = 0.f;
#pragma unroll
            for (int w = 0; w < 8; ++w) sv += red[tid * 8 + w];
            bcf[8 + tid] = sv;
        }
        __syncthreads();
        probs4[tid] = make_float4(e[0] / bcf[8], e[1] / bcf[9],
                                  e[2] / bcf[10], e[3] / bcf[11]);
        __syncthreads();

        // ---- soft = probs @ codebook; split k-range across the two halves ----
        {
            const int d    = tid & 127;
            const int half = tid >> 7;
            const int ks   = half * 128;
            float4 sacc = make_float4(0.f, 0.f, 0.f, 0.f);
#pragma unroll 8
            for (int k = 0; k < 128; ++k) {
                const int kk = ks + k;
                float  c = cb_s[kk * PAD + d];
                float4 p = probs4[kk];
                sacc.x = fmaf(p.x, c, sacc.x);
                sacc.y = fmaf(p.y, c, sacc.y);
                sacc.z = fmaf(p.z, c, sacc.z);
                sacc.w = fmaf(p.w, c, sacc.w);
            }
            if (half == 1) softp4[d] = sacc;
            __syncthreads();
            if (half == 0) {
                float4 o = softp4[d];
                float soft[4] = {sacc.x + o.x, sacc.y + o.y,
                                 sacc.z + o.z, sacc.w + o.w};
#pragma unroll
                for (int j = 0; j < 4; ++j) {
                    float spv = ((float*)sp4)[d * 4 + j];
                    float h   = cb_s[bci[j] * PAD + d];
                    float u = spv - soft[j]; acc1 = fmaf(u, u, acc1);
                    float v = spv - h;       acc2 = fmaf(v, v, acc2);
                    float w = soft[j] - h;   acc3 = fmaf(w, w, acc3);
                }
            }
        }
        __syncthreads();   // protect sp4/probs4/red for next group
    }

    // ---- block reduce loss partials ----
#pragma unroll
    for (int off = 16; off; off >>= 1) {
        acc1 += __shfl_down_sync(0xffffffffu, acc1, off);
        acc2 += __shfl_down_sync(0xffffffffu, acc2, off);
        acc3 += __shfl_down_sync(0xffffffffu, acc3, off);
    }
    if (lane == 0) {
        red[warp] = acc1; red[8 + warp] = acc2; red[16 + warp] = acc3;
    }
    __syncthreads();
    if (tid == 0) {
        float a1 = 0.f, a2 = 0.f, a3 = 0.f;
#pragma unroll
        for (int w = 0; w < 8; ++w) { a1 += red[w]; a2 += red[8 + w]; a3 += red[16 + w]; }
        atomicAdd(&g_acc[0], (double)a1);
        atomicAdd(&g_acc[1], (double)a2);
        atomicAdd(&g_acc[2], (double)a3);
    }
}

// ---------------------------------------------------------------------------
// Kernel 3: reg = sum over (i,j) of (R R^T - I)^2 ; 8 rows of i per block
// ---------------------------------------------------------------------------
__global__ void __launch_bounds__(256) reg_kernel(const float* __restrict__ R)
{
    __shared__ float  ri[8][D_];
    __shared__ double dred[256];
    const int i0 = blockIdx.x * 8;

    for (int idx = threadIdx.x; idx < 8 * D_; idx += 256)
        ri[idx >> 9][idx & 511] = R[(size_t)(i0 + (idx >> 9)) * D_ + (idx & 511)];
    __syncthreads();

    double local = 0.0;
    for (int j = threadIdx.x; j < D_; j += 256) {
        const float4* rj = (const float4*)(R + (size_t)j * D_);
        float acc[8];
#pragma unroll
        for (int i = 0; i < 8; ++i) acc[i] = 0.f;
        for (int k4 = 0; k4 < D_ / 4; ++k4) {
            float4 b = __ldg(&rj[k4]);
#pragma unroll
            for (int i = 0; i < 8; ++i) {
                acc[i] = fmaf(ri[i][k4 * 4 + 0], b.x, acc[i]);
                acc[i] = fmaf(ri[i][k4 * 4 + 1], b.y, acc[i]);
                acc[i] = fmaf(ri[i][k4 * 4 + 2], b.z, acc[i]);
                acc[i] = fmaf(ri[i][k4 * 4 + 3], b.w, acc[i]);
            }
        }
#pragma unroll
        for (int i = 0; i < 8; ++i) {
            float gv = acc[i] - ((i0 + i) == j ? 1.f : 0.f);
            local += (double)gv * (double)gv;
        }
    }
    dred[threadIdx.x] = local;
    __syncthreads();
    for (int s = 128; s > 0; s >>= 1) {
        if (threadIdx.x < s) dred[threadIdx.x] += dred[threadIdx.x + s];
        __syncthreads();
    }
    if (threadIdx.x == 0) atomicAdd(&g_acc[3], dred[0]);
}

// ---------------------------------------------------------------------------
// Kernel 4: finalize loss
// ---------------------------------------------------------------------------
__global__ void finalize_kernel(float* __restrict__ out)
{
    if (threadIdx.x == 0) {
        const double invA = 1.0 / ((double)N_ * (double)DM_);
        double loss = 0.1 * (g_acc[0] * invA)
                    +       (g_acc[1] * invA)
                    + 0.1 * (g_acc[2] * invA)
                    + 0.01 * (g_acc[3] / ((double)D_ * (double)D_));
        out[(size_t)N_ * M_] = (float)loss;
    }
}

// ---------------------------------------------------------------------------
extern "C" void kernel_launch(void* const* d_in, const int* in_sizes, int n_in,
                              void* d_out, int out_size)
{
    // Identify inputs by size (robust to ordering): x=N*D, codebook=M*K*DM, rotate=D*D
    const float* x   = nullptr;
    const float* cbk = nullptr;
    const float* rot = nullptr;
    for (int i = 0; i < n_in; ++i) {
        if (in_sizes[i] == N_ * D_)            x   = (const float*)d_in[i];
        else if (in_sizes[i] == M_ * K_ * DM_) cbk = (const float*)d_in[i];
        else if (in_sizes[i] == D_ * D_)       rot = (const float*)d_in[i];
    }
    if (!x)   x   = (const float*)d_in[0];
    if (!cbk) cbk = (const float*)d_in[1];
    if (!rot) rot = (const float*)d_in[2];

    float* out = (float*)d_out;

    cudaFuncSetAttribute(dist_kernel,
                         cudaFuncAttributeMaxDynamicSharedMemorySize, SMEM_BYTES);

    zero_acc_kernel<<<1, 32>>>();
    sgemm_xr_kernel<<<dim3(D_ / 128, N_ / 128), 256>>>(x, rot);
    dist_kernel<<<dim3(N_ / TILE_N, M_), 256, SMEM_BYTES>>>(cbk, out);
    reg_kernel<<<D_ / 8, 256>>>(rot);
    if (out_size > N_ * M_) finalize_kernel<<<1, 32>>>(out);
}

// round 6
// speedup vs baseline: 2.0164x; 2.0164x over previous
#include <cuda_runtime.h>
#include <math.h>

#define N_  131072
#define D_  512
#define M_  4
#define K_  256
#define DM_ 128

// Scratch: xr = x @ rotate (268 MB). __device__ globals are the sanctioned scratch.
__device__ float  g_xr[N_ * D_];
__device__ double g_acc[4];   // s_soft, s_hard, s_joint, s_reg

// ---------------------------------------------------------------------------
// f32x2 packed helpers (sm_103a FFMA2 path — only reachable via PTX f32x2)
// ---------------------------------------------------------------------------
__device__ __forceinline__ void ffma2(unsigned long long& d,
                                      unsigned long long a,
                                      unsigned long long b) {
    asm("fma.rn.f32x2 %0, %1, %2, %0;" : "+l"(d) : "l"(a), "l"(b));
}
__device__ __forceinline__ unsigned long long dup2(float x) {
    unsigned long long r;
    asm("mov.b64 %0, {%1, %2};" : "=l"(r) : "f"(x), "f"(x));
    return r;
}
__device__ __forceinline__ float2 unpk2(unsigned long long v) {
    float2 f;
    asm("mov.b64 {%0, %1}, %2;" : "=f"(f.x), "=f"(f.y) : "l"(v));
    return f;
}

// ---------------------------------------------------------------------------
// Kernel 0: zero accumulators
// ---------------------------------------------------------------------------
__global__ void zero_acc_kernel() {
    if (threadIdx.x < 4) g_acc[threadIdx.x] = 0.0;
}

// ---------------------------------------------------------------------------
// Kernel 1: xr = x @ rotate, fp32 via FFMA2. 128x128 tile, BK=8, 256 thr, 8x8.
// Accumulation order per output element identical to the scalar R4 version
// (ascending k), so g_xr is bitwise identical to the known-good kernel.
// ---------------------------------------------------------------------------
__global__ void __launch_bounds__(256, 2) sgemm_xr_kernel(
    const float* __restrict__ A, const float* __restrict__ B)
{
    __shared__ float As[8][128];
    __shared__ float Bs[8][128];

    const int bx = blockIdx.x;          // D_/128 = 4
    const int by = blockIdx.y;          // N_/128 = 1024
    const int tid = threadIdx.x;
    const int tx = tid & 15;
    const int ty = tid >> 4;

    const float* Ablk = A + (size_t)by * 128 * D_;
    const float* Bblk = B + bx * 128;

    const int arow = tid >> 1;
    const int acol = (tid & 1) * 4;
    const int brow = tid >> 5;
    const int bcol = (tid & 31) * 4;

    unsigned long long acc[8][4];
#pragma unroll
    for (int i = 0; i < 8; ++i)
#pragma unroll
        for (int j = 0; j < 4; ++j) acc[i][j] = 0ULL;

    for (int k0 = 0; k0 < D_; k0 += 8) {
        float4 av = *(const float4*)(Ablk + (size_t)arow * D_ + k0 + acol);
        float4 bv = *(const float4*)(Bblk + (size_t)(k0 + brow) * D_ + bcol);
        As[acol + 0][arow] = av.x;
        As[acol + 1][arow] = av.y;
        As[acol + 2][arow] = av.z;
        As[acol + 3][arow] = av.w;
        *(float4*)&Bs[brow][bcol] = bv;
        __syncthreads();

#pragma unroll
        for (int kk = 0; kk < 8; ++kk) {
            float4 a0 = *(const float4*)&As[kk][ty * 8];
            float4 a1 = *(const float4*)&As[kk][ty * 8 + 4];
            const unsigned long long* bp =
                (const unsigned long long*)&Bs[kk][tx * 8];
            unsigned long long b0 = bp[0], b1 = bp[1], b2 = bp[2], b3 = bp[3];
            unsigned long long ad[8] = {dup2(a0.x), dup2(a0.y), dup2(a0.z), dup2(a0.w),
                                        dup2(a1.x), dup2(a1.y), dup2(a1.z), dup2(a1.w)};
#pragma unroll
            for (int i = 0; i < 8; ++i) {
                ffma2(acc[i][0], ad[i], b0);
                ffma2(acc[i][1], ad[i], b1);
                ffma2(acc[i][2], ad[i], b2);
                ffma2(acc[i][3], ad[i], b3);
            }
        }
        __syncthreads();
    }

#pragma unroll
    for (int i = 0; i < 8; ++i) {
        const int row = by * 128 + ty * 8 + i;
        float* cp = g_xr + (size_t)row * D_ + bx * 128 + tx * 8;
        float2 c0 = unpk2(acc[i][0]);
        float2 c1 = unpk2(acc[i][1]);
        float2 c2 = unpk2(acc[i][2]);
        float2 c3 = unpk2(acc[i][3]);
        *(float4*)cp       = make_float4(c0.x, c0.y, c1.x, c1.y);
        *(float4*)(cp + 4) = make_float4(c2.x, c2.y, c3.x, c3.y);
    }
}

// ---------------------------------------------------------------------------
// Kernel 2: distances/softmax/argmax/losses.
// Block = (128-row n-tile, m). 256 threads. Group = 16 rows.
// Phase A: xc[k][16 rows] via FFMA2 (thread = 2 ks x 8 rows), stored RAW.
// Phase B: warp-per-row: x2 (R4-exact chain), dist = x2 - 2*xc + c2
//          (R4-exact expression -> bit-matching argmax), argmin,
//          cutoff-compacted softmax, soft/hard losses.
// ---------------------------------------------------------------------------
#define CBT_S   258
#define SP_S    20
#define DT_S    258
#define TILE_N  128
#define CUT     20.0f

#define SMEM_FLOATS (128*CBT_S + 256 + 128*SP_S + 16*DT_S + 16*256 + 32)
#define SMEM_BYTES  (SMEM_FLOATS * 4)

__device__ __forceinline__ unsigned fmap(float f) {
    unsigned b = __float_as_uint(f);
    return (b & 0x80000000u) ? ~b : (b | 0x80000000u);
}
__device__ __forceinline__ float funmap(unsigned u) {
    unsigned b = (u & 0x80000000u) ? (u & 0x7FFFFFFFu) : ~u;
    return __uint_as_float(b);
}

__global__ void __launch_bounds__(256) dist_kernel(
    const float* __restrict__ cb, float* __restrict__ out)
{
    extern __shared__ float sm[];
    float* cbT = sm;                         // [128][258] d-major codebook
    float* c2s = cbT + 128 * CBT_S;          // [256]
    float* sps = c2s + 256;                  // [128][20]  sp interleaved by row
    float* dts = sps + 128 * SP_S;           // [16][258]  xc rows / e-list
    int*   kix = (int*)(dts + 16 * DT_S);    // [16][256]  candidate k indices
    float* red = (float*)(kix + 16 * 256);   // [32]

    const int m    = blockIdx.y;
    const int tid  = threadIdx.x;
    const int lane = tid & 31;
    const int warp = tid >> 5;

    // ---- build cbT (d-major) + c2 ----
    {
        const float* cbm = cb + (size_t)m * K_ * DM_;
        const int k = tid;
        float c2 = 0.f;
#pragma unroll 8
        for (int dg = 0; dg < 32; ++dg) {
            float4 v = *(const float4*)(cbm + (size_t)k * DM_ + dg * 4);
            cbT[(dg * 4 + 0) * CBT_S + k] = v.x;
            cbT[(dg * 4 + 1) * CBT_S + k] = v.y;
            cbT[(dg * 4 + 2) * CBT_S + k] = v.z;
            cbT[(dg * 4 + 3) * CBT_S + k] = v.w;
            c2 = fmaf(v.x, v.x, c2); c2 = fmaf(v.y, v.y, c2);
            c2 = fmaf(v.z, v.z, c2); c2 = fmaf(v.w, v.w, c2);
        }
        c2s[k] = c2;
    }
    __syncthreads();

    const int kp = tid & 127;
    const int k0 = kp * 2;
    const int rh = tid >> 7;          // 0/1 -> rows rh*8 .. rh*8+7
    const int nbase = blockIdx.x * TILE_N;

    float la = 0.f, lb = 0.f, lc = 0.f;   // loss partials

    for (int g = 0; g < TILE_N / 16; ++g) {
        const int n0 = nbase + g * 16;

        // ---- load sp: 16 rows x 128 d, interleaved sps[d][row] ----
        {
            const int j  = tid & 15;
            const int dg = tid >> 4;          // 0..15, ds = dg*8
            const float* src = g_xr + (size_t)(n0 + j) * D_ + m * DM_ + dg * 8;
            float4 v0 = *(const float4*)src;
            float4 v1 = *(const float4*)(src + 4);
            const int b = dg * 8 * SP_S + j;
            sps[b]            = v0.x; sps[b +     SP_S] = v0.y;
            sps[b + 2 * SP_S] = v0.z; sps[b + 3 * SP_S] = v0.w;
            sps[b + 4 * SP_S] = v1.x; sps[b + 5 * SP_S] = v1.y;
            sps[b + 6 * SP_S] = v1.z; sps[b + 7 * SP_S] = v1.w;
        }
        __syncthreads();

        // ---- phase A: xc for (k0,k0+1) x 8 rows via FFMA2, stored raw ----
        unsigned long long acc[8];
#pragma unroll
        for (int i = 0; i < 8; ++i) acc[i] = 0ULL;

#pragma unroll 4
        for (int d = 0; d < DM_; ++d) {
            unsigned long long cpair =
                *(const unsigned long long*)(cbT + d * CBT_S + k0);
            float2 cf = unpk2(cpair);
            unsigned long long c0d = dup2(cf.x);
            unsigned long long c1d = dup2(cf.y);
            const ulonglong2* sp2 =
                (const ulonglong2*)(sps + d * SP_S + rh * 8);
            ulonglong2 s01 = sp2[0];
            ulonglong2 s23 = sp2[1];
            ffma2(acc[0], c0d, s01.x);
            ffma2(acc[1], c0d, s01.y);
            ffma2(acc[2], c0d, s23.x);
            ffma2(acc[3], c0d, s23.y);
            ffma2(acc[4], c1d, s01.x);
            ffma2(acc[5], c1d, s01.y);
            ffma2(acc[6], c1d, s23.x);
            ffma2(acc[7], c1d, s23.y);
        }
        {
#pragma unroll
            for (int p = 0; p < 4; ++p) {
                float2 a = unpk2(acc[p]);
                float2 b = unpk2(acc[4 + p]);
                const int r = rh * 8 + 2 * p;
                dts[(size_t)r * DT_S + k0]           = a.x;
                dts[(size_t)(r + 1) * DT_S + k0]     = a.y;
                dts[(size_t)r * DT_S + k0 + 1]       = b.x;
                dts[(size_t)(r + 1) * DT_S + k0 + 1] = b.y;
            }
        }
        __syncthreads();

        // ---- phase B: warp w handles rows 2w, 2w+1 ----
        for (int rr = 0; rr < 2; ++rr) {
            const int r = warp * 2 + rr;
            float* drow = dts + (size_t)r * DT_S;

            // x2 for this row — identical chain + reduction order to R4
            float v = 0.f;
#pragma unroll
            for (int d = lane; d < DM_; d += 32) {
                float s = sps[d * SP_S + r];
                v = fmaf(s, s, v);
            }
#pragma unroll
            for (int off = 16; off; off >>= 1)
                v += __shfl_down_sync(0xffffffffu, v, off);
            const float x2v = __shfl_sync(0xffffffffu, v, 0);

            // dist with the R4/jax expression shape (bit-matching argmax)
            float dv[8];
#pragma unroll
            for (int i = 0; i < 8; ++i) {
                const int k = lane + 32 * i;
                dv[i] = x2v - 2.f * drow[k] + c2s[k];
            }

            // local min, smallest k on ties
            float mn = dv[0]; int mk = lane;
#pragma unroll
            for (int i = 1; i < 8; ++i)
                if (dv[i] < mn) { mn = dv[i]; mk = lane + 32 * i; }

            // warp lexicographic (dist, k) min
            unsigned long long key =
                ((unsigned long long)fmap(mn) << 32) | (unsigned)mk;
#pragma unroll
            for (int off = 16; off; off >>= 1) {
                unsigned long long o = __shfl_down_sync(0xffffffffu, key, off);
                if (o < key) key = o;
            }
            key = __shfl_sync(0xffffffffu, key, 0);
            const int   kh   = (int)(key & 0xffffffffu);
            const float dmin = funmap((unsigned)(key >> 32));
            if (lane == 0)
                out[(size_t)(n0 + r) * M_ + m] = (float)kh;

            // candidates: dist - dmin < CUT (dropped softmax mass < 1e-6)
            float esum = 0.f;
            int base = 0;
#pragma unroll
            for (int i = 0; i < 8; ++i) {
                const float diff = dv[i] - dmin;
                const bool f = diff < CUT;
                const float e = f ? __expf(-diff) : 0.f;
                esum += e;
                const unsigned bal = __ballot_sync(0xffffffffu, f);
                if (f) {
                    const int pos = base + __popc(bal & ((1u << lane) - 1u));
                    drow[pos] = e;                 // reuse xc row as e-list
                    kix[r * 256 + pos] = lane + 32 * i;
                }
                base += __popc(bal);
            }
#pragma unroll
            for (int off = 16; off; off >>= 1)
                esum += __shfl_xor_sync(0xffffffffu, esum, off);
            const float inv = 1.f / esum;
            const int nnz = base;
            __syncwarp();

            // soft for this lane's 4 d's (d = lane + 32*i)
            float s0 = 0.f, s1 = 0.f, s2 = 0.f, s3 = 0.f;
            for (int s = 0; s < nnz; ++s) {
                const float p = drow[s] * inv;
                const float* cc = cbT + kix[r * 256 + s];
                s0 = fmaf(p, cc[(size_t)lane * CBT_S], s0);
                s1 = fmaf(p, cc[(size_t)(lane + 32) * CBT_S], s1);
                s2 = fmaf(p, cc[(size_t)(lane + 64) * CBT_S], s2);
                s3 = fmaf(p, cc[(size_t)(lane + 96) * CBT_S], s3);
            }

            // hard + loss partials
            const float* ch = cbT + kh;
            const float so[4] = {s0, s1, s2, s3};
#pragma unroll
            for (int i = 0; i < 4; ++i) {
                const int d = lane + 32 * i;
                const float sp = sps[d * SP_S + r];
                const float h  = ch[(size_t)d * CBT_S];
                const float u = sp - so[i]; la = fmaf(u, u, la);
                const float vv = sp - h;    lb = fmaf(vv, vv, lb);
                const float w = so[i] - h;  lc = fmaf(w, w, lc);
            }
        }
        __syncthreads();   // protect sps/dts for next group
    }

    // ---- block reduce loss partials ----
#pragma unroll
    for (int off = 16; off; off >>= 1) {
        la += __shfl_down_sync(0xffffffffu, la, off);
        lb += __shfl_down_sync(0xffffffffu, lb, off);
        lc += __shfl_down_sync(0xffffffffu, lc, off);
    }
    if (lane == 0) { red[warp] = la; red[8 + warp] = lb; red[16 + warp] = lc; }
    __syncthreads();
    if (tid == 0) {
        float a1 = 0.f, a2 = 0.f, a3 = 0.f;
#pragma unroll
        for (int w = 0; w < 8; ++w) {
            a1 += red[w]; a2 += red[8 + w]; a3 += red[16 + w];
        }
        atomicAdd(&g_acc[0], (double)a1);
        atomicAdd(&g_acc[1], (double)a2);
        atomicAdd(&g_acc[2], (double)a3);
    }
}

// ---------------------------------------------------------------------------
// Kernel 3: reg = sum (R R^T - I)^2 ; block = 8 i-rows x 256 j-cols
// ---------------------------------------------------------------------------
__global__ void __launch_bounds__(256) reg_kernel(const float* __restrict__ R)
{
    __shared__ float  ri[8][D_];
    __shared__ double dred[256];
    const int i0 = blockIdx.x * 8;
    const int j  = blockIdx.y * 256 + threadIdx.x;

    for (int idx = threadIdx.x; idx < 8 * D_; idx += 256)
        ri[idx >> 9][idx & 511] = R[(size_t)(i0 + (idx >> 9)) * D_ + (idx & 511)];
    __syncthreads();

    const float4* rj = (const float4*)(R + (size_t)j * D_);
    float acc[8];
#pragma unroll
    for (int i = 0; i < 8; ++i) acc[i] = 0.f;
    for (int k4 = 0; k4 < D_ / 4; ++k4) {
        float4 b = __ldg(&rj[k4]);
#pragma unroll
        for (int i = 0; i < 8; ++i) {
            acc[i] = fmaf(ri[i][k4 * 4 + 0], b.x, acc[i]);
            acc[i] = fmaf(ri[i][k4 * 4 + 1], b.y, acc[i]);
            acc[i] = fmaf(ri[i][k4 * 4 + 2], b.z, acc[i]);
            acc[i] = fmaf(ri[i][k4 * 4 + 3], b.w, acc[i]);
        }
    }
    double local = 0.0;
#pragma unroll
    for (int i = 0; i < 8; ++i) {
        float gv = acc[i] - ((i0 + i) == j ? 1.f : 0.f);
        local += (double)gv * (double)gv;
    }
    dred[threadIdx.x] = local;
    __syncthreads();
    for (int s = 128; s > 0; s >>= 1) {
        if (threadIdx.x < s) dred[threadIdx.x] += dred[threadIdx.x + s];
        __syncthreads();
    }
    if (threadIdx.x == 0) atomicAdd(&g_acc[3], dred[0]);
}

// ---------------------------------------------------------------------------
// Kernel 4: finalize loss
// ---------------------------------------------------------------------------
__global__ void finalize_kernel(float* __restrict__ out)
{
    if (threadIdx.x == 0) {
        const double invA = 1.0 / ((double)N_ * (double)DM_);
        double loss = 0.1 * (g_acc[0] * invA)
                    +       (g_acc[1] * invA)
                    + 0.1 * (g_acc[2] * invA)
                    + 0.01 * (g_acc[3] / ((double)D_ * (double)D_));
        out[(size_t)N_ * M_] = (float)loss;
    }
}

// ---------------------------------------------------------------------------
extern "C" void kernel_launch(void* const* d_in, const int* in_sizes, int n_in,
                              void* d_out, int out_size)
{
    const float* x   = nullptr;
    const float* cbk = nullptr;
    const float* rot = nullptr;
    for (int i = 0; i < n_in; ++i) {
        if (in_sizes[i] == N_ * D_)            x   = (const float*)d_in[i];
        else if (in_sizes[i] == M_ * K_ * DM_) cbk = (const float*)d_in[i];
        else if (in_sizes[i] == D_ * D_)       rot = (const float*)d_in[i];
    }
    if (!x)   x   = (const float*)d_in[0];
    if (!cbk) cbk = (const float*)d_in[1];
    if (!rot) rot = (const float*)d_in[2];

    float* out = (float*)d_out;

    cudaFuncSetAttribute(dist_kernel,
                         cudaFuncAttributeMaxDynamicSharedMemorySize, SMEM_BYTES);

    zero_acc_kernel<<<1, 32>>>();
    sgemm_xr_kernel<<<dim3(D_ / 128, N_ / 128), 256>>>(x, rot);
    dist_kernel<<<dim3(N_ / TILE_N, M_), 256, SMEM_BYTES>>>(cbk, out);
    reg_kernel<<<dim3(D_ / 8, 2), 256>>>(rot);
    if (out_size > N_ * M_) finalize_kernel<<<1, 32>>>(out);
}

// round 7
// speedup vs baseline: 2.0729x; 1.0280x over previous
#include <cuda_runtime.h>
#include <math.h>

#define N_  131072
#define D_  512
#define M_  4
#define K_  256
#define DM_ 128

// Scratch: xr = x @ rotate (268 MB). __device__ globals are the sanctioned scratch.
__device__ float  g_xr[N_ * D_];
__device__ double g_acc[4];   // s_soft, s_hard, s_joint, s_reg

// ---------------------------------------------------------------------------
// f32x2 packed helpers (sm_103a FFMA2 path — only reachable via PTX f32x2)
// ---------------------------------------------------------------------------
__device__ __forceinline__ void ffma2(unsigned long long& d,
                                      unsigned long long a,
                                      unsigned long long b) {
    asm("fma.rn.f32x2 %0, %1, %2, %0;" : "+l"(d) : "l"(a), "l"(b));
}
__device__ __forceinline__ unsigned long long dup2(float x) {
    unsigned long long r;
    asm("mov.b64 %0, {%1, %2};" : "=l"(r) : "f"(x), "f"(x));
    return r;
}
__device__ __forceinline__ float2 unpk2(unsigned long long v) {
    float2 f;
    asm("mov.b64 {%0, %1}, %2;" : "=f"(f.x), "=f"(f.y) : "l"(v));
    return f;
}

// ---------------------------------------------------------------------------
// Kernel 0: zero accumulators
// ---------------------------------------------------------------------------
__global__ void zero_acc_kernel() {
    if (threadIdx.x < 4) g_acc[threadIdx.x] = 0.0;
}

// ---------------------------------------------------------------------------
// Kernel 1: xr = x @ rotate, FFMA2, 128x128 tile, BK=8, 256 thr, 8x8/thread.
// Double-buffered smem + register prefetch: ONE __syncthreads per k-step.
// Per-element accumulation order (ascending k) identical to R4/R6 ->
// g_xr bitwise identical (argmax path depends on this).
// ---------------------------------------------------------------------------
__global__ void __launch_bounds__(256, 2) sgemm_xr_kernel(
    const float* __restrict__ A, const float* __restrict__ B)
{
    __shared__ float As[2][8][128];
    __shared__ float Bs[2][8][128];

    const int bx = blockIdx.x;          // D_/128 = 4
    const int by = blockIdx.y;          // N_/128 = 1024
    const int tid = threadIdx.x;
    const int tx = tid & 15;
    const int ty = tid >> 4;

    const float* Ablk = A + (size_t)by * 128 * D_;
    const float* Bblk = B + bx * 128;

    const int arow = tid >> 1;
    const int acol = (tid & 1) * 4;
    const int brow = tid >> 5;
    const int bcol = (tid & 31) * 4;

    unsigned long long acc[8][4];
#pragma unroll
    for (int i = 0; i < 8; ++i)
#pragma unroll
        for (int j = 0; j < 4; ++j) acc[i][j] = 0ULL;

    // prologue: stage tile 0 into buffer 0
    float4 av = *(const float4*)(Ablk + (size_t)arow * D_ + acol);
    float4 bv = *(const float4*)(Bblk + (size_t)brow * D_ + bcol);
    As[0][acol + 0][arow] = av.x;
    As[0][acol + 1][arow] = av.y;
    As[0][acol + 2][arow] = av.z;
    As[0][acol + 3][arow] = av.w;
    *(float4*)&Bs[0][brow][bcol] = bv;
    __syncthreads();

    for (int t = 0; t < 64; ++t) {
        const int cur = t & 1;
        if (t < 63) {
            const int k0 = (t + 1) * 8;
            av = *(const float4*)(Ablk + (size_t)arow * D_ + k0 + acol);
            bv = *(const float4*)(Bblk + (size_t)(k0 + brow) * D_ + bcol);
        }

#pragma unroll
        for (int kk = 0; kk < 8; ++kk) {
            float4 a0 = *(const float4*)&As[cur][kk][ty * 8];
            float4 a1 = *(const float4*)&As[cur][kk][ty * 8 + 4];
            const unsigned long long* bp =
                (const unsigned long long*)&Bs[cur][kk][tx * 8];
            unsigned long long b0 = bp[0], b1 = bp[1], b2 = bp[2], b3 = bp[3];
            unsigned long long ad[8] = {dup2(a0.x), dup2(a0.y), dup2(a0.z), dup2(a0.w),
                                        dup2(a1.x), dup2(a1.y), dup2(a1.z), dup2(a1.w)};
#pragma unroll
            for (int i = 0; i < 8; ++i) {
                ffma2(acc[i][0], ad[i], b0);
                ffma2(acc[i][1], ad[i], b1);
                ffma2(acc[i][2], ad[i], b2);
                ffma2(acc[i][3], ad[i], b3);
            }
        }

        if (t < 63) {
            const int nxt = cur ^ 1;
            As[nxt][acol + 0][arow] = av.x;
            As[nxt][acol + 1][arow] = av.y;
            As[nxt][acol + 2][arow] = av.z;
            As[nxt][acol + 3][arow] = av.w;
            *(float4*)&Bs[nxt][brow][bcol] = bv;
        }
        __syncthreads();
    }

#pragma unroll
    for (int i = 0; i < 8; ++i) {
        const int row = by * 128 + ty * 8 + i;
        float* cp = g_xr + (size_t)row * D_ + bx * 128 + tx * 8;
        float2 c0 = unpk2(acc[i][0]);
        float2 c1 = unpk2(acc[i][1]);
        float2 c2 = unpk2(acc[i][2]);
        float2 c3 = unpk2(acc[i][3]);
        *(float4*)cp       = make_float4(c0.x, c0.y, c1.x, c1.y);
        *(float4*)(cp + 4) = make_float4(c2.x, c2.y, c3.x, c3.y);
    }
}

// ---------------------------------------------------------------------------
// Kernel 2: distances/softmax/argmax/losses.
// Block = (128-row n-tile, m). 256 threads. Group = 32 rows.
// Phase A: xc via FFMA2, thread = 2 ks x 16 rows (LDS drops to 75% of fma
//          budget -> fma-bound). Raw xc to smem.
// Phase B: warp handles 4 rows: x2 (R4-exact chain), dist = x2 - 2*xc + c2
//          (R4-exact expression), argmin + tie-break, cutoff-compacted
//          softmax, soft/hard losses.
// ---------------------------------------------------------------------------
#define CBT_S   258
#define SP_S    36
#define DT_S    258
#define GROUP   32
#define TILE_N  128
#define CUT     20.0f

#define SMEM_FLOATS (128*CBT_S + 256 + 128*SP_S + GROUP*DT_S + GROUP*256 + 32)
#define SMEM_BYTES  (SMEM_FLOATS * 4)

__device__ __forceinline__ unsigned fmap(float f) {
    unsigned b = __float_as_uint(f);
    return (b & 0x80000000u) ? ~b : (b | 0x80000000u);
}
__device__ __forceinline__ float funmap(unsigned u) {
    unsigned b = (u & 0x80000000u) ? (u & 0x7FFFFFFFu) : ~u;
    return __uint_as_float(b);
}

__global__ void __launch_bounds__(256) dist_kernel(
    const float* __restrict__ cb, float* __restrict__ out)
{
    extern __shared__ float sm[];
    float* cbT = sm;                         // [128][258] d-major codebook
    float* c2s = cbT + 128 * CBT_S;          // [256]
    float* sps = c2s + 256;                  // [128][36]  sp interleaved by row
    float* dts = sps + 128 * SP_S;           // [32][258]  xc rows / e-list
    int*   kix = (int*)(dts + GROUP * DT_S); // [32][256]  candidate k indices
    float* red = (float*)(kix + GROUP * 256);// [32]

    const int m    = blockIdx.y;
    const int tid  = threadIdx.x;
    const int lane = tid & 31;
    const int warp = tid >> 5;

    // ---- build cbT (d-major) + c2 (chain identical to R6) ----
    {
        const float* cbm = cb + (size_t)m * K_ * DM_;
        const int k = tid;
        float c2 = 0.f;
#pragma unroll 8
        for (int dg = 0; dg < 32; ++dg) {
            float4 v = *(const float4*)(cbm + (size_t)k * DM_ + dg * 4);
            cbT[(dg * 4 + 0) * CBT_S + k] = v.x;
            cbT[(dg * 4 + 1) * CBT_S + k] = v.y;
            cbT[(dg * 4 + 2) * CBT_S + k] = v.z;
            cbT[(dg * 4 + 3) * CBT_S + k] = v.w;
            c2 = fmaf(v.x, v.x, c2); c2 = fmaf(v.y, v.y, c2);
            c2 = fmaf(v.z, v.z, c2); c2 = fmaf(v.w, v.w, c2);
        }
        c2s[k] = c2;
    }
    __syncthreads();

    const int kp = tid & 127;
    const int k0 = kp * 2;
    const int rh = tid >> 7;          // 0/1 -> rows rh*16 .. rh*16+15
    const int nbase = blockIdx.x * TILE_N;

    float la = 0.f, lb = 0.f, lc = 0.f;   // loss partials

    for (int g = 0; g < TILE_N / GROUP; ++g) {
        const int n0 = nbase + g * GROUP;

        // ---- load sp: 32 rows x 128 d, interleaved sps[d][row] ----
        {
            const int j  = tid & 31;          // row
            const int dg = tid >> 5;          // 0..7 -> d base dg*16
            const float* src = g_xr + (size_t)(n0 + j) * D_ + m * DM_ + dg * 16;
            float4 v0 = *(const float4*)(src);
            float4 v1 = *(const float4*)(src + 4);
            float4 v2 = *(const float4*)(src + 8);
            float4 v3 = *(const float4*)(src + 12);
            const int b = dg * 16 * SP_S + j;
            sps[b +  0 * SP_S] = v0.x; sps[b +  1 * SP_S] = v0.y;
            sps[b +  2 * SP_S] = v0.z; sps[b +  3 * SP_S] = v0.w;
            sps[b +  4 * SP_S] = v1.x; sps[b +  5 * SP_S] = v1.y;
            sps[b +  6 * SP_S] = v1.z; sps[b +  7 * SP_S] = v1.w;
            sps[b +  8 * SP_S] = v2.x; sps[b +  9 * SP_S] = v2.y;
            sps[b + 10 * SP_S] = v2.z; sps[b + 11 * SP_S] = v2.w;
            sps[b + 12 * SP_S] = v3.x; sps[b + 13 * SP_S] = v3.y;
            sps[b + 14 * SP_S] = v3.z; sps[b + 15 * SP_S] = v3.w;
        }
        __syncthreads();

        // ---- phase A: xc for (k0,k0+1) x 16 rows via FFMA2 ----
        unsigned long long acc0[8], acc1[8];
#pragma unroll
        for (int i = 0; i < 8; ++i) { acc0[i] = 0ULL; acc1[i] = 0ULL; }

#pragma unroll 2
        for (int d = 0; d < DM_; ++d) {
            unsigned long long cpair =
                *(const unsigned long long*)(cbT + d * CBT_S + k0);
            float2 cf = unpk2(cpair);
            unsigned long long c0d = dup2(cf.x);
            unsigned long long c1d = dup2(cf.y);
            const ulonglong2* sp2 =
                (const ulonglong2*)(sps + d * SP_S + rh * 16);
            ulonglong2 sA = sp2[0];
            ulonglong2 sB = sp2[1];
            ffma2(acc0[0], c0d, sA.x); ffma2(acc0[1], c0d, sA.y);
            ffma2(acc0[2], c0d, sB.x); ffma2(acc0[3], c0d, sB.y);
            ffma2(acc1[0], c1d, sA.x); ffma2(acc1[1], c1d, sA.y);
            ffma2(acc1[2], c1d, sB.x); ffma2(acc1[3], c1d, sB.y);
            ulonglong2 sC = sp2[2];
            ulonglong2 sD = sp2[3];
            ffma2(acc0[4], c0d, sC.x); ffma2(acc0[5], c0d, sC.y);
            ffma2(acc0[6], c0d, sD.x); ffma2(acc0[7], c0d, sD.y);
            ffma2(acc1[4], c1d, sC.x); ffma2(acc1[5], c1d, sC.y);
            ffma2(acc1[6], c1d, sD.x); ffma2(acc1[7], c1d, sD.y);
        }
        // store raw xc rows (k pair packed as one STS64 per row)
#pragma unroll
        for (int p = 0; p < 8; ++p) {
            float2 a = unpk2(acc0[p]);      // k0,  rows (2p, 2p+1)
            float2 b = unpk2(acc1[p]);      // k0+1
            const int r = rh * 16 + 2 * p;
            *(float2*)&dts[(size_t)r * DT_S + k0]       = make_float2(a.x, b.x);
            *(float2*)&dts[(size_t)(r + 1) * DT_S + k0] = make_float2(a.y, b.y);
        }
        __syncthreads();

        // ---- phase B: warp w handles rows 4w..4w+3 ----
        for (int rr = 0; rr < 4; ++rr) {
            const int r = warp * 4 + rr;
            float* drow = dts + (size_t)r * DT_S;

            // x2 — identical chain + reduction order to R4/R6
            float v = 0.f;
#pragma unroll
            for (int d = lane; d < DM_; d += 32) {
                float s = sps[d * SP_S + r];
                v = fmaf(s, s, v);
            }
#pragma unroll
            for (int off = 16; off; off >>= 1)
                v += __shfl_down_sync(0xffffffffu, v, off);
            const float x2v = __shfl_sync(0xffffffffu, v, 0);

            // dist with the R4/jax expression (bit-matching argmax)
            float dv[8];
#pragma unroll
            for (int i = 0; i < 8; ++i) {
                const int k = lane + 32 * i;
                dv[i] = x2v - 2.f * drow[k] + c2s[k];
            }

            // local min, smallest k on ties
            float mn = dv[0]; int mk = lane;
#pragma unroll
            for (int i = 1; i < 8; ++i)
                if (dv[i] < mn) { mn = dv[i]; mk = lane + 32 * i; }

            // warp lexicographic (dist, k) min
            unsigned long long key =
                ((unsigned long long)fmap(mn) << 32) | (unsigned)mk;
#pragma unroll
            for (int off = 16; off; off >>= 1) {
                unsigned long long o = __shfl_down_sync(0xffffffffu, key, off);
                if (o < key) key = o;
            }
            key = __shfl_sync(0xffffffffu, key, 0);
            const int   kh   = (int)(key & 0xffffffffu);
            const float dmin = funmap((unsigned)(key >> 32));
            if (lane == 0)
                out[(size_t)(n0 + r) * M_ + m] = (float)kh;

            // candidates: dist - dmin < CUT (dropped softmax mass < 1e-6)
            float esum = 0.f;
            int base = 0;
#pragma unroll
            for (int i = 0; i < 8; ++i) {
                const float diff = dv[i] - dmin;
                const bool f = diff < CUT;
                const float e = f ? __expf(-diff) : 0.f;
                esum += e;
                const unsigned bal = __ballot_sync(0xffffffffu, f);
                if (f) {
                    const int pos = base + __popc(bal & ((1u << lane) - 1u));
                    drow[pos] = e;                 // reuse xc row as e-list
                    kix[r * 256 + pos] = lane + 32 * i;
                }
                base += __popc(bal);
            }
#pragma unroll
            for (int off = 16; off; off >>= 1)
                esum += __shfl_xor_sync(0xffffffffu, esum, off);
            const float inv = 1.f / esum;
            const int nnz = base;
            __syncwarp();

            // soft for this lane's 4 d's
            float s0 = 0.f, s1 = 0.f, s2 = 0.f, s3 = 0.f;
            for (int s = 0; s < nnz; ++s) {
                const float p = drow[s] * inv;
                const float* cc = cbT + kix[r * 256 + s];
                s0 = fmaf(p, cc[(size_t)lane * CBT_S], s0);
                s1 = fmaf(p, cc[(size_t)(lane + 32) * CBT_S], s1);
                s2 = fmaf(p, cc[(size_t)(lane + 64) * CBT_S], s2);
                s3 = fmaf(p, cc[(size_t)(lane + 96) * CBT_S], s3);
            }

            // hard + loss partials
            const float* ch = cbT + kh;
            const float so[4] = {s0, s1, s2, s3};
#pragma unroll
            for (int i = 0; i < 4; ++i) {
                const int d = lane + 32 * i;
                const float sp = sps[d * SP_S + r];
                const float h  = ch[(size_t)d * CBT_S];
                const float u = sp - so[i]; la = fmaf(u, u, la);
                const float vv = sp - h;    lb = fmaf(vv, vv, lb);
                const float w = so[i] - h;  lc = fmaf(w, w, lc);
            }
        }
        __syncthreads();   // protect sps/dts for next group
    }

    // ---- block reduce loss partials ----
#pragma unroll
    for (int off = 16; off; off >>= 1) {
        la += __shfl_down_sync(0xffffffffu, la, off);
        lb += __shfl_down_sync(0xffffffffu, lb, off);
        lc += __shfl_down_sync(0xffffffffu, lc, off);
    }
    if (lane == 0) { red[warp] = la; red[8 + warp] = lb; red[16 + warp] = lc; }
    __syncthreads();
    if (tid == 0) {
        float a1 = 0.f, a2 = 0.f, a3 = 0.f;
#pragma unroll
        for (int w = 0; w < 8; ++w) {
            a1 += red[w]; a2 += red[8 + w]; a3 += red[16 + w];
        }
        atomicAdd(&g_acc[0], (double)a1);
        atomicAdd(&g_acc[1], (double)a2);
        atomicAdd(&g_acc[2], (double)a3);
    }
}

// ---------------------------------------------------------------------------
// Kernel 3: reg = sum (R R^T - I)^2 ; block = 8 i-rows x 256 j-cols
// ---------------------------------------------------------------------------
__global__ void __launch_bounds__(256) reg_kernel(const float* __restrict__ R)
{
    __shared__ float  ri[8][D_];
    __shared__ double dred[256];
    const int i0 = blockIdx.x * 8;
    const int j  = blockIdx.y * 256 + threadIdx.x;

    for (int idx = threadIdx.x; idx < 8 * D_; idx += 256)
        ri[idx >> 9][idx & 511] = R[(size_t)(i0 + (idx >> 9)) * D_ + (idx & 511)];
    __syncthreads();

    const float4* rj = (const float4*)(R + (size_t)j * D_);
    float acc[8];
#pragma unroll
    for (int i = 0; i < 8; ++i) acc[i] = 0.f;
    for (int k4 = 0; k4 < D_ / 4; ++k4) {
        float4 b = __ldg(&rj[k4]);
#pragma unroll
        for (int i = 0; i < 8; ++i) {
            acc[i] = fmaf(ri[i][k4 * 4 + 0], b.x, acc[i]);
            acc[i] = fmaf(ri[i][k4 * 4 + 1], b.y, acc[i]);
            acc[i] = fmaf(ri[i][k4 * 4 + 2], b.z, acc[i]);
            acc[i] = fmaf(ri[i][k4 * 4 + 3], b.w, acc[i]);
        }
    }
    double local = 0.0;
#pragma unroll
    for (int i = 0; i < 8; ++i) {
        float gv = acc[i] - ((i0 + i) == j ? 1.f : 0.f);
        local += (double)gv * (double)gv;
    }
    dred[threadIdx.x] = local;
    __syncthreads();
    for (int s = 128; s > 0; s >>= 1) {
        if (threadIdx.x < s) dred[threadIdx.x] += dred[threadIdx.x + s];
        __syncthreads();
    }
    if (threadIdx.x == 0) atomicAdd(&g_acc[3], dred[0]);
}

// ---------------------------------------------------------------------------
// Kernel 4: finalize loss
// ---------------------------------------------------------------------------
__global__ void finalize_kernel(float* __restrict__ out)
{
    if (threadIdx.x == 0) {
        const double invA = 1.0 / ((double)N_ * (double)DM_);
        double loss = 0.1 * (g_acc[0] * invA)
                    +       (g_acc[1] * invA)
                    + 0.1 * (g_acc[2] * invA)
                    + 0.01 * (g_acc[3] / ((double)D_ * (double)D_));
        out[(size_t)N_ * M_] = (float)loss;
    }
}

// ---------------------------------------------------------------------------
extern "C" void kernel_launch(void* const* d_in, const int* in_sizes, int n_in,
                              void* d_out, int out_size)
{
    const float* x   = nullptr;
    const float* cbk = nullptr;
    const float* rot = nullptr;
    for (int i = 0; i < n_in; ++i) {
        if (in_sizes[i] == N_ * D_)            x   = (const float*)d_in[i];
        else if (in_sizes[i] == M_ * K_ * DM_) cbk = (const float*)d_in[i];
        else if (in_sizes[i] == D_ * D_)       rot = (const float*)d_in[i];
    }
    if (!x)   x   = (const float*)d_in[0];
    if (!cbk) cbk = (const float*)d_in[1];
    if (!rot) rot = (const float*)d_in[2];

    float* out = (float*)d_out;

    cudaFuncSetAttribute(dist_kernel,
                         cudaFuncAttributeMaxDynamicSharedMemorySize, SMEM_BYTES);

    zero_acc_kernel<<<1, 32>>>();
    sgemm_xr_kernel<<<dim3(D_ / 128, N_ / 128), 256>>>(x, rot);
    dist_kernel<<<dim3(N_ / TILE_N, M_), 256, SMEM_BYTES>>>(cbk, out);
    reg_kernel<<<dim3(D_ / 8, 2), 256>>>(rot);
    if (out_size > N_ * M_) finalize_kernel<<<1, 32>>>(out);
}